// round 16
// baseline (speedup 1.0000x reference)
#include <cuda_runtime.h>
#include <math.h>

#define T_SEQ   8192
#define NBATCH  2
#define NROWS   (NBATCH * T_SEQ)   // 16384
#define WIN     448                // gamma^448/(1-gamma) ~ 2e-5: safe at 1e-3
#define L2G     (-0.04580369f)     // log2(0.96875)

// ---------------- scratch (device globals; no allocs allowed) ----------------
__device__ float g_Q[NROWS * 64];
__device__ float g_K[NROWS * 64];
__device__ float g_V[NROWS * 64];
__device__ float g_O0[NROWS * 64];   // partial O, window half 0
__device__ float g_O1[NROWS * 64];   // partial O, window half 1

__device__ __forceinline__ float to_tf32(float x) {
    unsigned u; asm("cvt.rna.tf32.f32 %0, %1;" : "=r"(u) : "f"(x));
    return __uint_as_float(u);
}

// m16n8k8 tf32 warp MMA (family-agnostic PTX, compiles for compute_103)
__device__ __forceinline__ void mma_tf32(float& d0, float& d1, float& d2, float& d3,
                                         unsigned a0, unsigned a1, unsigned a2, unsigned a3,
                                         unsigned b0, unsigned b1) {
    asm volatile("mma.sync.aligned.m16n8k8.row.col.f32.tf32.tf32.f32 "
                 "{%0,%1,%2,%3}, {%4,%5,%6,%7}, {%8,%9}, {%0,%1,%2,%3};"
                 : "+f"(d0), "+f"(d1), "+f"(d2), "+f"(d3)
                 : "r"(a0), "r"(a1), "r"(a2), "r"(a3), "r"(b0), "r"(b1));
}

// =================== Kernel 1: QKV proj (3xTF32 tensor-core) =================
#define LDXP 68    // X smem pad: frag banks gi*4+ti4 -> conflict-free
#define LDW  200   // W smem pad: 200 mod 32 = 8 -> frag banks ti4*8+gi -> CF
#define PROJ_SMEM ((64 * LDXP + 64 * LDW) * 4)   // 68608 B

__global__ __launch_bounds__(256, 2) void proj_kernel(
    const float* __restrict__ X,
    const float* __restrict__ WQ,
    const float* __restrict__ WK,
    const float* __restrict__ WV)
{
    extern __shared__ float sm[];
    float* Xs = sm;                // [64][LDXP]
    float* Ws = sm + 64 * LDXP;    // [64 k][LDW], cols 0..191 = WQ|WK|WV

    const int tid  = threadIdx.x;
    const int lane = tid & 31;
    const int w    = tid >> 5;
    const int gi   = lane >> 2;
    const int ti4  = lane & 3;
    const int wr   = w & 3;        // row group
    const int wh   = w >> 2;       // column half
    const int r0   = blockIdx.x * 64;

    for (int idx = tid; idx < 64 * 16; idx += 256) {
        int row = idx >> 4, c4 = (idx & 15) << 2;
        *(float4*)&Xs[row * LDXP + c4] = *(const float4*)&X[(r0 + row) * 64 + c4];
    }
    {
        const float* Wsrc[3] = {WQ, WK, WV};
        #pragma unroll
        for (int m = 0; m < 3; m++)
            for (int idx = tid; idx < 64 * 16; idx += 256) {
                int row = idx >> 4, c4 = (idx & 15) << 2;
                *(float4*)&Ws[row * LDW + m * 64 + c4] =
                    *(const float4*)&Wsrc[m][row * 64 + c4];
            }
    }
    __syncthreads();

    const int qrow = wr * 16 + gi;
    unsigned ahi[8][4], alo[8][4];
    #pragma unroll
    for (int k0 = 0; k0 < 8; k0++) {
        float xv[4];
        xv[0] = Xs[qrow * LDXP + k0 * 8 + ti4];
        xv[1] = Xs[(qrow + 8) * LDXP + k0 * 8 + ti4];
        xv[2] = Xs[qrow * LDXP + k0 * 8 + ti4 + 4];
        xv[3] = Xs[(qrow + 8) * LDXP + k0 * 8 + ti4 + 4];
        #pragma unroll
        for (int u = 0; u < 4; u++) {
            float hi = to_tf32(xv[u]);
            ahi[k0][u] = __float_as_uint(hi);
            alo[k0][u] = __float_as_uint(to_tf32(xv[u] - hi));
        }
    }

    float* outp[3] = {g_Q, g_K, g_V};
    for (int m = 0; m < 3; m++) {
        float accA[4][4], accB[4][4];
        #pragma unroll
        for (int nt = 0; nt < 4; nt++)
            #pragma unroll
            for (int u = 0; u < 4; u++) { accA[nt][u] = 0.f; accB[nt][u] = 0.f; }

        #pragma unroll
        for (int k0 = 0; k0 < 8; k0++) {
            #pragma unroll
            for (int ntl = 0; ntl < 4; ntl++) {
                const int ncol = m * 64 + (wh * 4 + ntl) * 8 + gi;
                float b0f = Ws[(k0 * 8 + ti4) * LDW + ncol];
                float b1f = Ws[(k0 * 8 + ti4 + 4) * LDW + ncol];
                float b0h = to_tf32(b0f), b1h = to_tf32(b1f);
                unsigned ub0h = __float_as_uint(b0h);
                unsigned ub1h = __float_as_uint(b1h);
                unsigned ub0l = __float_as_uint(to_tf32(b0f - b0h));
                unsigned ub1l = __float_as_uint(to_tf32(b1f - b1h));
                mma_tf32(accA[ntl][0], accA[ntl][1], accA[ntl][2], accA[ntl][3],
                         ahi[k0][0], ahi[k0][1], ahi[k0][2], ahi[k0][3], ub0h, ub1h);
                mma_tf32(accB[ntl][0], accB[ntl][1], accB[ntl][2], accB[ntl][3],
                         ahi[k0][0], ahi[k0][1], ahi[k0][2], ahi[k0][3], ub0l, ub1l);
                mma_tf32(accB[ntl][0], accB[ntl][1], accB[ntl][2], accB[ntl][3],
                         alo[k0][0], alo[k0][1], alo[k0][2], alo[k0][3], ub0h, ub1h);
            }
        }
        float* op = outp[m];
        #pragma unroll
        for (int ntl = 0; ntl < 4; ntl++) {
            int col = (wh * 4 + ntl) * 8 + 2 * ti4;
            *(float2*)&op[(r0 + qrow) * 64 + col] =
                make_float2(accA[ntl][0] + accB[ntl][0], accA[ntl][1] + accB[ntl][1]);
            *(float2*)&op[(r0 + qrow + 8) * 64 + col] =
                make_float2(accA[ntl][2] + accB[ntl][2], accA[ntl][3] + accB[ntl][3]);
        }
    }
}

// ===== Kernel 2: warp-MMA tf32 attention, inter-CTA window split (grid 512) ==
// CTA = (64-row q-block, window half). 4 warps x 16 rows, 128 threads.
// Half 0: tiles [0, nh); half 1: [nh, nt_all) incl. diagonal. Raw partial O
// to g_O0/g_O1; combine+GN in kernel 3. 70.9KB smem, 168 regs -> 3 CTAs/SM.
#define LDP 68   // pad for Q/K/S
#define LDV 72   // pad for V

#define SM_BINV 0
#define SM_QS   64                       // [64][LDP] persistent Q
#define SM_SS   (SM_QS + 64 * LDP)       // [64][LDP] S buffer
#define SM_KS   (SM_SS + 64 * LDP)       // [64][LDP]
#define SM_VS   (SM_KS + 64 * LDP)       // [64][LDV]
#define ATTN_SMEM ((SM_VS + 64 * LDV) * 4)   // 70912 B

__global__ __launch_bounds__(128, 3) void attn_kernel()
{
    extern __shared__ float sm[];
    float* binv = sm + SM_BINV;
    float* Qs   = sm + SM_QS;
    float* Ks   = sm + SM_KS;
    float* Vs   = sm + SM_VS;

    const int tid  = threadIdx.x;
    const int lane = tid & 31;
    const int w    = tid >> 5;
    const int gi   = lane >> 2;   // 0..7
    const int ti4  = lane & 3;    // 0..3

    const int blk = blockIdx.x >> 1;
    const int hf  = blockIdx.x & 1;
    const int r0  = blk * 64;
    const int b   = r0 >> 13;
    const int t0  = r0 & (T_SEQ - 1);
    const int bT  = b << 13;

    if (tid < 64) binv[tid] = exp2f(-(float)tid * L2G);   // gamma^-j

    // ---- stage Q (tf32), persistent across tiles ----
    for (int idx = tid; idx < 64 * 16; idx += 128) {
        int row = idx >> 4, c4 = (idx & 15) << 2;
        float4 v = *(const float4*)&g_Q[(r0 + row) * 64 + c4];
        v.x = to_tf32(v.x); v.y = to_tf32(v.y); v.z = to_tf32(v.z); v.w = to_tf32(v.w);
        *(float4*)&Qs[row * LDP + c4] = v;
    }
    __syncthreads();

    const int qr = w * 16;
    float* sw = sm + SM_SS + qr * LDP;              // warp-private S rows
    const float* qf = &Qs[(qr + gi) * LDP + ti4];   // A-frag base (Q)
    const float* sf = sw + gi * LDP + ti4;          // A-frag base (S)

    float o[8][4];
    #pragma unroll
    for (int nt = 0; nt < 8; nt++)
        #pragma unroll
        for (int u = 0; u < 4; u++) o[nt][u] = 0.f;

    int ks = t0 - WIN; if (ks < 0) ks = 0;
    const int nt_all = (t0 + 64 - ks) >> 6;
    const int nh     = nt_all >> 1;
    const int i_beg  = hf ? nh : 0;
    const int i_end  = hf ? nt_all : nh;

    for (int it = i_beg; it < i_end; it++) {
        const int s0 = ks + (it << 6);

        // ---- stage K, V tiles (tf32) ----
        for (int idx = tid; idx < 64 * 16; idx += 128) {
            int key = idx >> 4, c4 = (idx & 15) << 2;
            float4 kv = *(const float4*)&g_K[(bT + s0 + key) * 64 + c4];
            kv.x = to_tf32(kv.x); kv.y = to_tf32(kv.y);
            kv.z = to_tf32(kv.z); kv.w = to_tf32(kv.w);
            *(float4*)&Ks[key * LDP + c4] = kv;
            float4 vv = *(const float4*)&g_V[(bT + s0 + key) * 64 + c4];
            vv.x = to_tf32(vv.x); vv.y = to_tf32(vv.y);
            vv.z = to_tf32(vv.z); vv.w = to_tf32(vv.w);
            *(float4*)&Vs[key * LDV + c4] = vv;
        }
        __syncthreads();

        const int   dr0 = t0 + qr + gi - s0;
        const float ai0 = exp2f((float)dr0 * L2G);
        const float ai1 = exp2f((float)(dr0 + 8) * L2G);

        // ---- stage 1: S = Q K^T (k0-outer; Q-frag loaded per k0) ----
        float s[8][4];
        #pragma unroll
        for (int nt = 0; nt < 8; nt++)
            #pragma unroll
            for (int u = 0; u < 4; u++) s[nt][u] = 0.f;

        #pragma unroll
        for (int k0 = 0; k0 < 8; k0++) {
            unsigned a0 = __float_as_uint(qf[k0 * 8]);
            unsigned a1 = __float_as_uint(qf[k0 * 8 + 8 * LDP]);
            unsigned a2 = __float_as_uint(qf[k0 * 8 + 4]);
            unsigned a3 = __float_as_uint(qf[k0 * 8 + 8 * LDP + 4]);
            #pragma unroll
            for (int nt = 0; nt < 8; nt++) {
                int ba = (nt * 8 + gi) * LDP + k0 * 8 + ti4;
                unsigned b0 = __float_as_uint(Ks[ba]);
                unsigned b1 = __float_as_uint(Ks[ba + 4]);
                mma_tf32(s[nt][0], s[nt][1], s[nt][2], s[nt][3],
                         a0, a1, a2, a3, b0, b1);
            }
        }

        // ---- decay + causal mask, tf32, to S buffer ----
        #pragma unroll
        for (int nt = 0; nt < 8; nt++) {
            const int je = nt * 8 + 2 * ti4, jo = je + 1;
            const float be = binv[je], bo = binv[jo];
            float c0 = (dr0     >= je) ? s[nt][0] * ai0 * be : 0.f;
            float c1 = (dr0     >= jo) ? s[nt][1] * ai0 * bo : 0.f;
            float c2 = (dr0 + 8 >= je) ? s[nt][2] * ai1 * be : 0.f;
            float c3 = (dr0 + 8 >= jo) ? s[nt][3] * ai1 * bo : 0.f;
            *(float2*)&sw[gi * LDP + je]       = make_float2(to_tf32(c0), to_tf32(c1));
            *(float2*)&sw[(gi + 8) * LDP + je] = make_float2(to_tf32(c2), to_tf32(c3));
        }
        __syncwarp();

        // ---- stage 2: O += S V (k0-outer; S-frag loaded per k0) ----
        #pragma unroll
        for (int k0 = 0; k0 < 8; k0++) {
            unsigned a0 = __float_as_uint(sf[k0 * 8]);
            unsigned a1 = __float_as_uint(sf[k0 * 8 + 8 * LDP]);
            unsigned a2 = __float_as_uint(sf[k0 * 8 + 4]);
            unsigned a3 = __float_as_uint(sf[k0 * 8 + 8 * LDP + 4]);
            #pragma unroll
            for (int nt = 0; nt < 8; nt++) {
                int va = (k0 * 8 + ti4) * LDV + nt * 8 + gi;
                unsigned b0 = __float_as_uint(Vs[va]);
                unsigned b1 = __float_as_uint(Vs[va + 4 * LDV]);
                mma_tf32(o[nt][0], o[nt][1], o[nt][2], o[nt][3],
                         a0, a1, a2, a3, b0, b1);
            }
        }
        __syncthreads();   // compute done before next tile's K/V overwrite
    }

    // ---- write raw partial O ----
    float* op = hf ? g_O1 : g_O0;
    const int row0 = r0 + qr + gi;
    #pragma unroll
    for (int nt = 0; nt < 8; nt++) {
        int col = nt * 8 + 2 * ti4;
        *(float2*)&op[row0 * 64 + col]       = make_float2(o[nt][0], o[nt][1]);
        *(float2*)&op[(row0 + 8) * 64 + col] = make_float2(o[nt][2], o[nt][3]);
    }
}

// ============== Kernel 3: combine halves + GroupNorm + transpose =============
__global__ __launch_bounds__(256) void gn_kernel(
    const float* __restrict__ gw, const float* __restrict__ gb,
    float* __restrict__ out)
{
    const int tid = threadIdx.x;
    const int tt  = tid & 31;
    const int g   = tid >> 5;            // 0..7
    const int row = blockIdx.x * 32 + tt;
    const int b   = row >> 13;
    const int t   = row & (T_SEQ - 1);

    const float* x0 = &g_O0[row * 64 + g * 8];
    const float* x1 = &g_O1[row * 64 + g * 8];
    float v[8];
    float s = 0.f;
    #pragma unroll
    for (int u = 0; u < 8; u += 4) {
        float4 a = *(const float4*)&x0[u];
        float4 c = *(const float4*)&x1[u];
        v[u + 0] = a.x + c.x; v[u + 1] = a.y + c.y;
        v[u + 2] = a.z + c.z; v[u + 3] = a.w + c.w;
        s += v[u] + v[u + 1] + v[u + 2] + v[u + 3];
    }
    float mu = s * 0.125f;
    float var = 0.f;
    #pragma unroll
    for (int u = 0; u < 8; u++) { float d = v[u] - mu; var = fmaf(d, d, var); }
    var *= 0.125f;
    float rs = rsqrtf(var + 1e-6f);

    #pragma unroll
    for (int u = 0; u < 8; u++) {
        int c = g * 8 + u;
        out[(size_t)b * T_SEQ * 64 + (size_t)c * T_SEQ + t] =
            (v[u] - mu) * rs * gw[c] + gb[c];
    }
}

// =============================================================================
extern "C" void kernel_launch(void* const* d_in, const int* in_sizes, int n_in,
                              void* d_out, int out_size)
{
    (void)in_sizes; (void)n_in; (void)out_size;
    const float* X  = (const float*)d_in[0];
    const float* WQ = (const float*)d_in[1];
    const float* WK = (const float*)d_in[2];
    const float* WV = (const float*)d_in[3];
    const float* gw = (const float*)d_in[4];
    const float* gb = (const float*)d_in[5];
    float* out = (float*)d_out;

    cudaFuncSetAttribute(proj_kernel, cudaFuncAttributeMaxDynamicSharedMemorySize, PROJ_SMEM);
    cudaFuncSetAttribute(attn_kernel, cudaFuncAttributeMaxDynamicSharedMemorySize, ATTN_SMEM);

    proj_kernel<<<NROWS / 64, 256, PROJ_SMEM>>>(X, WQ, WK, WV);
    attn_kernel<<<NROWS / 32, 128, ATTN_SMEM>>>();
    gn_kernel<<<NROWS / 32, 256>>>(gw, gb, out);
}